// round 3
// baseline (speedup 1.0000x reference)
#include <cuda_runtime.h>
#include <math.h>

#define NN 20000
#define EE 320000
#define DIM 128
#define GDIM 512          // HEADS * DIM
#define NHEADS 4
#define NB 16
#define NACT 10
#define NEG_SLOPE 0.2f

// ---------------- scratch (static __device__, no allocs) ----------------
static __device__ int   d_deg[NN];
static __device__ int   d_rowptr[NN + 1];
static __device__ int   d_wptr[NN];
static __device__ int   d_csrsrc[EE];
static __device__ float d_nm[NN * DIM];          // neighbor mean
static __device__ float d_h[NN * DIM];           // SAGE output
static __device__ float d_g[(size_t)NN * GDIM];  // GAT transformed feats
static __device__ float d_as[NN * NHEADS];
static __device__ float d_ad[NN * NHEADS];
static __device__ float d_h2[NN * DIM];          // GAT output
static __device__ float d_pool[NB * DIM];
static __device__ float d_pcnt[NB];

__device__ __forceinline__ float elu(float v) {
    return v > 0.f ? v : __expf(v) - 1.f;
}

// ---------------- CSR build ----------------

__global__ void k_zero() {
    int i = blockIdx.x * blockDim.x + threadIdx.x;
    if (i < NN) { d_deg[i] = 0; d_wptr[i] = 0; }
    if (i < NB * DIM) d_pool[i] = 0.f;
    if (i < NB) d_pcnt[i] = 0.f;
}

__global__ void k_count(const int* __restrict__ ei) {
    int i = blockIdx.x * blockDim.x + threadIdx.x;
    if (i < EE) atomicAdd(&d_deg[ei[EE + i]], 1);
}

// single-block scan, warp-shuffle based
__global__ void k_scan() {
    __shared__ int wsum[32];
    __shared__ int carry_s;
    int tid = threadIdx.x, lane = tid & 31, wid = tid >> 5;
    if (tid == 0) { carry_s = 0; d_rowptr[0] = 0; }
    __syncthreads();
    for (int base = 0; base < NN; base += 1024) {
        int i = base + tid;
        int v = (i < NN) ? d_deg[i] : 0;
        int s = v;
#pragma unroll
        for (int o = 1; o < 32; o <<= 1) {
            int t = __shfl_up_sync(0xffffffffu, s, o);
            if (lane >= o) s += t;
        }
        if (lane == 31) wsum[wid] = s;
        __syncthreads();
        if (wid == 0) {
            int w = wsum[lane];
#pragma unroll
            for (int o = 1; o < 32; o <<= 1) {
                int t = __shfl_up_sync(0xffffffffu, w, o);
                if (lane >= o) w += t;
            }
            wsum[lane] = w;
        }
        __syncthreads();
        int off = (wid > 0) ? wsum[wid - 1] : 0;
        int inc = s + off + carry_s;
        if (i < NN) d_rowptr[i + 1] = inc;
        __syncthreads();
        if (tid == 1023) carry_s = inc;
        __syncthreads();
    }
}

__global__ void k_scatter(const int* __restrict__ ei) {
    int i = blockIdx.x * blockDim.x + threadIdx.x;
    if (i < EE) {
        int s = ei[i];
        int t = ei[EE + i];
        int pos = d_rowptr[t] + atomicAdd(&d_wptr[t], 1);
        d_csrsrc[pos] = s;
    }
}

// ---------------- SAGE ----------------

// neighbor mean: one block per node, 4 warps stride edges, float4 loads
__global__ void k_sage_agg(const float* __restrict__ x) {
    int n = blockIdx.x;
    int tid = threadIdx.x, w = tid >> 5, l = tid & 31;
    int beg = d_rowptr[n], end = d_rowptr[n + 1];
    const float4* x4 = (const float4*)x;
    float4 acc = make_float4(0.f, 0.f, 0.f, 0.f);
    for (int j = beg + w; j < end; j += 4) {
        int s = d_csrsrc[j];
        float4 v = x4[(size_t)s * 32 + l];
        acc.x += v.x; acc.y += v.y; acc.z += v.z; acc.w += v.w;
    }
    __shared__ float4 part[4][32];
    part[w][l] = acc;
    __syncthreads();
    if (tid < 32) {
        float4 a = part[0][tid], b = part[1][tid], c = part[2][tid], d = part[3][tid];
        float inv = 1.f / fmaxf((float)(end - beg), 1.f);
        float4 r;
        r.x = (a.x + b.x + c.x + d.x) * inv;
        r.y = (a.y + b.y + c.y + d.y) * inv;
        r.z = (a.z + b.z + c.z + d.z) * inv;
        r.w = (a.w + b.w + c.w + d.w) * inv;
        ((float4*)d_nm)[n * 32 + tid] = r;
    }
}

// h = elu(nm@W_l + x@W_r + b) ; 16 nodes per block, 128 threads
__global__ void k_sage_lin(const float* __restrict__ x,
                           const float* __restrict__ Wl,
                           const float* __restrict__ Wr,
                           const float* __restrict__ bs) {
    __shared__ float4 sm4[16][32], sx4[16][32];
    int tid = threadIdx.x;
    int n0 = blockIdx.x * 16;
#pragma unroll
    for (int i = 0; i < 4; i++) {
        int idx = i * 128 + tid;
        int row = idx >> 5, col = idx & 31;
        sm4[row][col] = ((const float4*)d_nm)[(n0 + row) * 32 + col];
        sx4[row][col] = ((const float4*)x)[(size_t)(n0 + row) * 32 + col];
    }
    __syncthreads();
    float b = bs[tid];
    float acc[16];
#pragma unroll
    for (int r = 0; r < 16; r++) acc[r] = b;
    for (int kk = 0; kk < 32; kk++) {
        float wl0 = Wl[(4 * kk + 0) * DIM + tid];
        float wl1 = Wl[(4 * kk + 1) * DIM + tid];
        float wl2 = Wl[(4 * kk + 2) * DIM + tid];
        float wl3 = Wl[(4 * kk + 3) * DIM + tid];
        float wr0 = Wr[(4 * kk + 0) * DIM + tid];
        float wr1 = Wr[(4 * kk + 1) * DIM + tid];
        float wr2 = Wr[(4 * kk + 2) * DIM + tid];
        float wr3 = Wr[(4 * kk + 3) * DIM + tid];
#pragma unroll
        for (int r = 0; r < 16; r++) {
            float4 m = sm4[r][kk];
            float4 xx = sx4[r][kk];
            acc[r] += m.x * wl0 + m.y * wl1 + m.z * wl2 + m.w * wl3
                    + xx.x * wr0 + xx.y * wr1 + xx.z * wr2 + xx.w * wr3;
        }
    }
#pragma unroll
    for (int r = 0; r < 16; r++)
        d_h[(n0 + r) * DIM + tid] = elu(acc[r]);
}

// ---------------- GAT ----------------

// g = h@W_gat ; 16 nodes per block, 512 threads
__global__ void k_gat_lin(const float* __restrict__ Wg) {
    __shared__ float4 sh4[16][32];
    int tid = threadIdx.x;
    int n0 = blockIdx.x * 16;
    {
        int row = tid >> 5, col = tid & 31;
        sh4[row][col] = ((const float4*)d_h)[(n0 + row) * 32 + col];
    }
    __syncthreads();
    float acc[16];
#pragma unroll
    for (int r = 0; r < 16; r++) acc[r] = 0.f;
    for (int kk = 0; kk < 32; kk++) {
        float w0 = Wg[(4 * kk + 0) * GDIM + tid];
        float w1 = Wg[(4 * kk + 1) * GDIM + tid];
        float w2 = Wg[(4 * kk + 2) * GDIM + tid];
        float w3 = Wg[(4 * kk + 3) * GDIM + tid];
#pragma unroll
        for (int r = 0; r < 16; r++) {
            float4 m = sh4[r][kk];
            acc[r] += m.x * w0 + m.y * w1 + m.z * w2 + m.w * w3;
        }
    }
#pragma unroll
    for (int r = 0; r < 16; r++)
        d_g[(size_t)(n0 + r) * GDIM + tid] = acc[r];
}

// a_s, a_d: one warp per (node, head)
__global__ void k_attn(const float* __restrict__ att_s,
                       const float* __restrict__ att_d) {
    int gw = (blockIdx.x * blockDim.x + threadIdx.x) >> 5;
    if (gw >= NN * NHEADS) return;
    int l = threadIdx.x & 31;
    int n = gw >> 2, h = gw & 3;
    float4 gv = ((const float4*)d_g)[(size_t)n * 128 + h * 32 + l];
    float4 sv = ((const float4*)att_s)[h * 32 + l];
    float4 dv = ((const float4*)att_d)[h * 32 + l];
    float as = gv.x * sv.x + gv.y * sv.y + gv.z * sv.z + gv.w * sv.w;
    float ad = gv.x * dv.x + gv.y * dv.y + gv.z * dv.z + gv.w * dv.w;
#pragma unroll
    for (int o = 16; o; o >>= 1) {
        as += __shfl_xor_sync(0xffffffffu, as, o);
        ad += __shfl_xor_sync(0xffffffffu, ad, o);
    }
    if (l == 0) { d_as[n * 4 + h] = as; d_ad[n * 4 + h] = ad; }
}

// GAT softmax-aggregate per dst node + fused mean-pool accumulate
__global__ void k_gat_agg(const int* __restrict__ batch,
                          const float* __restrict__ b_gat) {
    __shared__ float smax[NHEADS];
    __shared__ float4 sacc[128];
    int n = blockIdx.x, t = threadIdx.x, h = t >> 5, l = t & 31;
    int beg = d_rowptr[n], end = d_rowptr[n + 1];
    float ad_h = d_ad[n * 4 + h];

    // max phase: warp h handles head h
    float mx = -1e30f;
    for (int j = beg + l; j < end; j += 32) {
        int s = d_csrsrc[j];
        float v = d_as[s * 4 + h] + ad_h;
        v = v > 0.f ? v : NEG_SLOPE * v;
        mx = fmaxf(mx, v);
    }
#pragma unroll
    for (int o = 16; o; o >>= 1)
        mx = fmaxf(mx, __shfl_xor_sync(0xffffffffu, mx, o));
    if (l == 0) smax[h] = mx;
    __syncthreads();
    float m = smax[h];

    const float4* g4 = (const float4*)d_g;
    const float4* as4 = (const float4*)d_as;
    float4 acc = make_float4(0.f, 0.f, 0.f, 0.f);
    float den = 0.f;
    for (int j = beg; j < end; j++) {
        int s = d_csrsrc[j];
        float4 av = as4[s];
        float a = (h == 0) ? av.x : (h == 1) ? av.y : (h == 2) ? av.z : av.w;
        float v = a + ad_h;
        v = v > 0.f ? v : NEG_SLOPE * v;
        float e = __expf(v - m);
        den += e;
        float4 gv = g4[(size_t)s * 128 + t];
        acc.x += e * gv.x; acc.y += e * gv.y;
        acc.z += e * gv.z; acc.w += e * gv.w;
    }
    float inv = 1.f / (den + 1e-16f);
    float4 sc;
    sc.x = acc.x * inv; sc.y = acc.y * inv;
    sc.z = acc.z * inv; sc.w = acc.w * inv;
    sacc[t] = sc;
    __syncthreads();
    if (t < 32) {
        float4 a = sacc[t], b = sacc[32 + t], c = sacc[64 + t], d = sacc[96 + t];
        float4 bg = ((const float4*)b_gat)[t];
        float4 o;
        o.x = elu((a.x + b.x + c.x + d.x) * 0.25f + bg.x);
        o.y = elu((a.y + b.y + c.y + d.y) * 0.25f + bg.y);
        o.z = elu((a.z + b.z + c.z + d.z) * 0.25f + bg.z);
        o.w = elu((a.w + b.w + c.w + d.w) * 0.25f + bg.w);
        ((float4*)d_h2)[n * 32 + t] = o;
        int bb = batch[n];
        atomicAdd(&d_pool[bb * DIM + 4 * t + 0], o.x);
        atomicAdd(&d_pool[bb * DIM + 4 * t + 1], o.y);
        atomicAdd(&d_pool[bb * DIM + 4 * t + 2], o.z);
        atomicAdd(&d_pool[bb * DIM + 4 * t + 3], o.w);
        if (t == 0) atomicAdd(&d_pcnt[bb], 1.f);
    }
}

// ---------------- output heads ----------------

__global__ void k_heads(const float* __restrict__ Ww, const float* __restrict__ bw,
                        const float* __restrict__ Wt, const float* __restrict__ bt,
                        float* __restrict__ out) {
    int w = (blockIdx.x * blockDim.x + threadIdx.x) >> 5;
    if (w >= NN) return;
    int lane = threadIdx.x & 31;
    const float* Wv;
    float bias;
    if (w < NN - 10) { Wv = Ww; bias = bw[0]; }
    else             { Wv = Wt; bias = bt[0]; }
    float4 hv = ((const float4*)d_h2)[w * 32 + lane];
    float4 wv = ((const float4*)Wv)[lane];
    float a = hv.x * wv.x + hv.y * wv.y + hv.z * wv.z + hv.w * wv.w;
#pragma unroll
    for (int off = 16; off > 0; off >>= 1)
        a += __shfl_xor_sync(0xffffffffu, a, off);
    if (lane == 0) out[w] = 1.f / (1.f + __expf(-(a + bias)));
}

__global__ void k_logits(const float* __restrict__ Wa, const float* __restrict__ ba,
                         float* __restrict__ out) {
    __shared__ float sp[DIM];
    int b = blockIdx.x;
    int tid = threadIdx.x;
    float cnt = fmaxf(d_pcnt[b], 1.f);
    sp[tid] = d_pool[b * DIM + tid] / cnt;
    __syncthreads();
    if (tid < NACT) {
        float a = ba[tid];
#pragma unroll 8
        for (int c = 0; c < DIM; c++) a += sp[c] * Wa[c * NACT + tid];
        out[NN + b * NACT + tid] = a;
    }
}

// ---------------- launch ----------------
extern "C" void kernel_launch(void* const* d_in, const int* in_sizes, int n_in,
                              void* d_out, int out_size) {
    const float* x     = (const float*)d_in[0];
    const int*   ei    = (const int*)d_in[1];
    const int*   batch = (const int*)d_in[2];
    const float* Wl   = (const float*)d_in[3];
    const float* Wr   = (const float*)d_in[4];
    const float* bs   = (const float*)d_in[5];
    const float* Wg   = (const float*)d_in[6];
    const float* ats  = (const float*)d_in[7];
    const float* atd  = (const float*)d_in[8];
    const float* bg   = (const float*)d_in[9];
    const float* Ww   = (const float*)d_in[10];
    const float* bw   = (const float*)d_in[11];
    const float* Wt   = (const float*)d_in[12];
    const float* bt   = (const float*)d_in[13];
    const float* Wa   = (const float*)d_in[14];
    const float* ba   = (const float*)d_in[15];
    float* out = (float*)d_out;

    k_zero<<<(NN + 255) / 256, 256>>>();
    k_count<<<EE / 256, 256>>>(ei);
    k_scan<<<1, 1024>>>();
    k_scatter<<<EE / 256, 256>>>(ei);
    k_sage_agg<<<NN, DIM>>>(x);
    k_sage_lin<<<NN / 16, DIM>>>(x, Wl, Wr, bs);
    k_gat_lin<<<NN / 16, GDIM>>>(Wg);
    k_attn<<<(NN * NHEADS * 32) / 256, 256>>>(ats, atd);
    k_gat_agg<<<NN, DIM>>>(batch, bg);
    k_heads<<<(NN * 32 + 127) / 128, 128>>>(Ww, bw, Wt, bt, out);
    k_logits<<<NB, DIM>>>(Wa, ba, out);
}